// round 6
// baseline (speedup 1.0000x reference)
#include <cuda_runtime.h>
#include <math.h>
#include <stdint.h>

#define Nn    20000
#define Ee    320000
#define FIN   128
#define H1c   64
#define H2c   128
#define HEADSc 8
#define NCc   40
#define K1c   16000
#define K2c   12800

#define CDIV(a,b) (((a)+(b)-1)/(b))
#define SCAN_NB 32
#define CM_NB   40

// ---------------------------------------------------------------------------
// Device scratch
// ---------------------------------------------------------------------------
__device__ float d_aggr[K1c*H1c];
__device__ int   d_cnt[Nn];
__device__ int   d_rowptr[Nn+1];
__device__ int   d_wp[Nn];
__device__ int   d_csr[Ee];
__device__ float d_gP[Nn*H2c];
__device__ float d_gQR[Nn*2*H2c];
__device__ float d_h1[Nn*H1c];
__device__ float d_hp1[K1c*H1c];
__device__ float d_h2[K1c*H2c];
__device__ float d_hp2[K2c*H2c];
__device__ float d_xh[K2c*HEADSc*H2c];     // 12800 x 1024
__device__ float d_va[FIN*16];
__device__ float d_alad[K2c*16];
__device__ float d_att[Ee*HEADSc];
__device__ float d_attself[K2c*HEADSc];
__device__ float d_gin[K2c*H2c];
__device__ float d_y1[K2c*H1c];
__device__ float d_o1[K2c*H1c];
__device__ float d_y2[K2c*NCc];
__device__ float d_o2[K2c*NCc];
__device__ float d_dinv[K2c];
__device__ float d_score[Nn];
__device__ int   d_keep[Nn];
__device__ int   d_nid[Nn];
__device__ int   d_src1[Ee], d_dst1[Ee], d_src2[Ee], d_dst2[Ee];
__device__ int   d_Ecnt[2];

// persistent-grid shared state (volatile: cross-SM coherence via L2)
__device__ volatile int      d_barcnt = 0;
__device__ volatile unsigned d_bargen = 0;
__device__ volatile int      d_partials[64];
__device__ volatile unsigned g_hist[256];
__device__ volatile unsigned g_prefix;
__device__ volatile int      g_krem;
__device__ volatile float    g_gvec[NCc];

// ---------------------------------------------------------------------------
// Grid barrier (all blocks co-resident: grids <= 40 blocks of 256 threads)
// ---------------------------------------------------------------------------
__device__ __forceinline__ void gridbar(int nb){
    __syncthreads();
    if (threadIdx.x == 0) {
        __threadfence();
        unsigned gen = d_bargen;
        if (atomicAdd((int*)&d_barcnt, 1) == nb - 1) {
            d_barcnt = 0;
            __threadfence();
            d_bargen = gen + 1;
        } else {
            while (d_bargen == gen) { }
        }
        __threadfence();
    }
    __syncthreads();
}

// inclusive block scan for 256 threads; total in warpsum[7] afterwards
__device__ __forceinline__ int blk_scan256(int v, int* warpsum){
    int tid = threadIdx.x, lane = tid & 31, wid = tid >> 5;
    #pragma unroll
    for (int o = 1; o < 32; o <<= 1) {
        int t = __shfl_up_sync(0xFFFFFFFFu, v, o);
        if (lane >= o) v += t;
    }
    if (lane == 31) warpsum[wid] = v;
    __syncthreads();
    if (tid < 8) {
        int s = warpsum[tid];
        #pragma unroll
        for (int o = 1; o < 8; o <<= 1) {
            int t = __shfl_up_sync(0xFFu, s, o);
            if (tid >= o) s += t;
        }
        warpsum[tid] = s;
    }
    __syncthreads();
    return v + (wid ? warpsum[wid-1] : 0);
}

// ---------------------------------------------------------------------------
// CSR build
// ---------------------------------------------------------------------------
__global__ void k_count(const int* __restrict__ dst, int* __restrict__ cnt,
                        const int* pE, int Emax){
    int e = blockIdx.x*blockDim.x + threadIdx.x;
    if (e >= Emax) return;
    int E = pE ? *pE : Emax;
    if (e < E) atomicAdd(&cnt[dst[e]], 1);
}

// persistent multi-block exclusive scan; single sweep (n <= 32768, n % 4 == 0).
// Also zeroes deg[0..nzero) in place after reading (nzero % 4 == 0).
__global__ void k_exscan_p(int* __restrict__ deg, int* __restrict__ rowptr,
                           int* __restrict__ wp, int n, int nzero){
    __shared__ int warpsum[8];
    int gt = blockIdx.x*256 + threadIdx.x;
    int i0 = gt*4;
    int4 v = make_int4(0,0,0,0);
    if (i0 < n) v = *reinterpret_cast<const int4*>(deg + i0);
    int s = v.x + v.y + v.z + v.w;
    int incl = blk_scan256(s, warpsum);
    if (threadIdx.x == 255) d_partials[blockIdx.x] = incl;
    if (i0 < nzero) *reinterpret_cast<int4*>(deg + i0) = make_int4(0,0,0,0);
    gridbar(SCAN_NB);
    if (blockIdx.x == 0 && threadIdx.x < SCAN_NB) {
        int p = d_partials[threadIdx.x];
        int t = p;
        #pragma unroll
        for (int o = 1; o < SCAN_NB; o <<= 1) {
            int q = __shfl_up_sync(0xFFFFFFFFu, t, o);
            if (threadIdx.x >= o) t += q;
        }
        d_partials[threadIdx.x] = t - p;          // exclusive
        if (threadIdx.x == SCAN_NB-1) rowptr[n] = t;
    }
    gridbar(SCAN_NB);
    int run = d_partials[blockIdx.x] + incl - s;
    if (i0 < n) {
        rowptr[i0]   = run; wp[i0]   = run; run += v.x;
        rowptr[i0+1] = run; wp[i0+1] = run; run += v.y;
        rowptr[i0+2] = run; wp[i0+2] = run; run += v.z;
        rowptr[i0+3] = run; wp[i0+3] = run;
    }
}

__global__ void k_fill(const int* __restrict__ src, const int* __restrict__ dst,
                       int* __restrict__ wp, int* __restrict__ csr,
                       const int* pE, int Emax){
    int e = blockIdx.x*blockDim.x + threadIdx.x;
    if (e >= Emax) return;
    int E = pE ? *pE : Emax;
    if (e >= E) return;
    int d = dst[e];
    int p = atomicAdd(&wp[d], 1);
    csr[p] = src[e];
}

// ---------------------------------------------------------------------------
// SAGE gathers (warp per node, 64 feats)
// ---------------------------------------------------------------------------
__global__ void k_sage1_gather(const int* __restrict__ rowptr, const int* __restrict__ csr,
                               const float* __restrict__ y, const float* __restrict__ QR,
                               const float* __restrict__ bl, const float* __restrict__ rb,
                               float* __restrict__ h, int n){
    int t = blockIdx.x*blockDim.x + threadIdx.x;
    int w = t >> 5, lane = t & 31;
    if (w >= n) return;
    int e0 = rowptr[w], e1 = rowptr[w+1];
    float a0 = 0.f, a1 = 0.f;
    for (int p = e0; p < e1; p++) {
        int s = csr[p];
        a0 += y[s*H1c + lane];
        a1 += y[s*H1c + 32 + lane];
    }
    float inv = 1.f / fmaxf((float)(e1 - e0), 1.f);
    a0 *= inv; a1 *= inv;
    const float* qr = QR + (size_t)w*2*H1c;
    h[w*H1c + lane]      = fmaxf(a0 + qr[lane]    + bl[lane],    0.f) + qr[H1c + lane]    + rb[lane];
    h[w*H1c + 32 + lane] = fmaxf(a1 + qr[32+lane] + bl[32+lane], 0.f) + qr[H1c + 32+lane] + rb[32+lane];
}

__global__ void k_mean_gather(const int* __restrict__ rowptr, const int* __restrict__ csr,
                              const float* __restrict__ x, float* __restrict__ out, int n){
    int t = blockIdx.x*blockDim.x + threadIdx.x;
    int w = t >> 5, lane = t & 31;
    if (w >= n) return;
    int e0 = rowptr[w], e1 = rowptr[w+1];
    float a0 = 0.f, a1 = 0.f;
    for (int p = e0; p < e1; p++) {
        int s = csr[p];
        a0 += x[s*H1c + lane];
        a1 += x[s*H1c + 32 + lane];
    }
    float inv = 1.f / fmaxf((float)(e1 - e0), 1.f);
    out[w*H1c + lane]      = a0 * inv;
    out[w*H1c + 32 + lane] = a1 * inv;
}

__global__ void k_sage_combine(const float* __restrict__ P, const float* __restrict__ QR,
                               const float* __restrict__ bl, const float* __restrict__ rb,
                               float* __restrict__ h, int n, int C){
    int i = blockIdx.x*blockDim.x + threadIdx.x;
    if (i >= n*C) return;
    int node = i / C, c = i % C;
    const float* qr = QR + (size_t)node*2*C;
    float v = P[i] + qr[c] + bl[c];
    h[i] = fmaxf(v, 0.f) + qr[C + c] + rb[c];
}

// ---------------------------------------------------------------------------
// SGEMM: C = A@B, 128x128 tile, BK=16, double-buffered, 8x8/thread quadrants.
// Optional B2 (dual weight: cols [0,Nh) from B, [Nh,2Nh) from B2). K % 16 == 0.
// ---------------------------------------------------------------------------
#define GBM 128
#define GBN 128
#define GBK 16
__global__ void __launch_bounds__(256)
k_gemm(const float* __restrict__ A, const float* __restrict__ B,
       const float* __restrict__ B2, float* __restrict__ C,
       int M, int N, int K, int Nh){
    __shared__ float As[2][GBK][GBM+4];
    __shared__ float Bs[2][GBK][GBN];
    int tid = threadIdx.x;                    // 256 threads
    int rowBase = blockIdx.y*GBM, colBase = blockIdx.x*GBN;
    int tr = tid >> 4, tc = tid & 15;
    int ar = tid >> 1, kseg = (tid & 1) * 8;
    int br = tid >> 4, bc0 = (tid & 15) * 8;
    float acc[8][8];
    #pragma unroll
    for (int i = 0; i < 8; i++)
        #pragma unroll
        for (int j = 0; j < 8; j++) acc[i][j] = 0.f;

    int nk = K / GBK;
    float4 pa0, pa1; float pb[8];
    {
        int gr = rowBase + ar;
        pa0 = make_float4(0.f,0.f,0.f,0.f); pa1 = pa0;
        if (gr < M) {
            pa0 = *reinterpret_cast<const float4*>(&A[(size_t)gr*K + kseg]);
            pa1 = *reinterpret_cast<const float4*>(&A[(size_t)gr*K + kseg + 4]);
        }
        #pragma unroll
        for (int j = 0; j < 8; j++) {
            int gc = colBase + bc0 + j;
            float v = 0.f;
            if (gc < N) {
                if (B2) v = (gc < Nh) ? B[(size_t)br*Nh + gc] : B2[(size_t)br*Nh + gc - Nh];
                else    v = B[(size_t)br*N + gc];
            }
            pb[j] = v;
        }
    }
    As[0][kseg+0][ar]=pa0.x; As[0][kseg+1][ar]=pa0.y; As[0][kseg+2][ar]=pa0.z; As[0][kseg+3][ar]=pa0.w;
    As[0][kseg+4][ar]=pa1.x; As[0][kseg+5][ar]=pa1.y; As[0][kseg+6][ar]=pa1.z; As[0][kseg+7][ar]=pa1.w;
    #pragma unroll
    for (int j = 0; j < 8; j++) Bs[0][br][bc0+j] = pb[j];
    __syncthreads();

    for (int kt = 0; kt < nk; kt++) {
        int cur = kt & 1;
        if (kt + 1 < nk) {
            int k0 = (kt+1)*GBK;
            int gr = rowBase + ar;
            pa0 = make_float4(0.f,0.f,0.f,0.f); pa1 = pa0;
            if (gr < M) {
                pa0 = *reinterpret_cast<const float4*>(&A[(size_t)gr*K + k0 + kseg]);
                pa1 = *reinterpret_cast<const float4*>(&A[(size_t)gr*K + k0 + kseg + 4]);
            }
            int gk = k0 + br;
            #pragma unroll
            for (int j = 0; j < 8; j++) {
                int gc = colBase + bc0 + j;
                float v = 0.f;
                if (gc < N) {
                    if (B2) v = (gc < Nh) ? B[(size_t)gk*Nh + gc] : B2[(size_t)gk*Nh + gc - Nh];
                    else    v = B[(size_t)gk*N + gc];
                }
                pb[j] = v;
            }
        }
        #pragma unroll
        for (int kk = 0; kk < GBK; kk++) {
            float a[8], b[8];
            #pragma unroll
            for (int i = 0; i < 4; i++) { a[i] = As[cur][kk][tr*4+i]; a[4+i] = As[cur][kk][64+tr*4+i]; }
            #pragma unroll
            for (int j = 0; j < 4; j++) { b[j] = Bs[cur][kk][tc*4+j]; b[4+j] = Bs[cur][kk][64+tc*4+j]; }
            #pragma unroll
            for (int i = 0; i < 8; i++)
                #pragma unroll
                for (int j = 0; j < 8; j++) acc[i][j] += a[i]*b[j];
        }
        if (kt + 1 < nk) {
            int nb = 1 - cur;
            As[nb][kseg+0][ar]=pa0.x; As[nb][kseg+1][ar]=pa0.y; As[nb][kseg+2][ar]=pa0.z; As[nb][kseg+3][ar]=pa0.w;
            As[nb][kseg+4][ar]=pa1.x; As[nb][kseg+5][ar]=pa1.y; As[nb][kseg+6][ar]=pa1.z; As[nb][kseg+7][ar]=pa1.w;
            #pragma unroll
            for (int j = 0; j < 8; j++) Bs[nb][br][bc0+j] = pb[j];
        }
        __syncthreads();
    }
    #pragma unroll
    for (int i = 0; i < 8; i++) {
        int r = rowBase + ((i < 4) ? (tr*4 + i) : (64 + tr*4 + i - 4));
        if (r >= M) continue;
        #pragma unroll
        for (int j = 0; j < 8; j++) {
            int c = colBase + ((j < 4) ? (tc*4 + j) : (64 + tc*4 + j - 4));
            if (c < N) C[(size_t)r*N + c] = acc[i][j];
        }
    }
}

// ---------------------------------------------------------------------------
// TopK: score + persistent multi-block radix select
// ---------------------------------------------------------------------------
__global__ void k_score(const float* __restrict__ h, const float* __restrict__ w,
                        float* score, int n, int F){
    __shared__ float red[256];
    __shared__ float s_wni;
    float s = 0;
    for (int i = threadIdx.x; i < F; i += 256) { float v = w[i]; s += v*v; }
    red[threadIdx.x] = s; __syncthreads();
    for (int o = 128; o; o >>= 1) {
        if (threadIdx.x < o) red[threadIdx.x] += red[threadIdx.x+o];
        __syncthreads();
    }
    if (threadIdx.x == 0) s_wni = rsqrtf(red[0]);
    __syncthreads();
    int wrp = threadIdx.x >> 5, lane = threadIdx.x & 31;
    int node = blockIdx.x*8 + wrp;
    if (node >= n) return;
    const float* r = h + (size_t)node*F;
    float d = 0;
    for (int c = lane; c < F; c += 32) d += r[c]*w[c];
    #pragma unroll
    for (int o = 16; o; o >>= 1) d += __shfl_down_sync(0xFFFFFFFFu, d, o);
    if (!lane) score[node] = tanhf(d * s_wni);
}

__device__ __forceinline__ unsigned fkey(float f){
    unsigned u = __float_as_uint(f);
    return (u & 0x80000000u) ? ~u : (u | 0x80000000u);
}

// persistent select: 32 blocks x 256 threads; n <= 32768, n % 4 == 0
__global__ void k_select_p(const float* __restrict__ score, int n, int K,
                           int* __restrict__ keep, int* __restrict__ nid, int* ezero){
    __shared__ unsigned shist[256];
    __shared__ int warpsum[8];
    int tid = threadIdx.x;
    int gt = blockIdx.x*256 + tid;
    int i0 = gt*4;
    bool valid = i0 < n;
    unsigned kk[4] = {0u,0u,0u,0u};
    if (valid) {
        float4 v = *reinterpret_cast<const float4*>(score + i0);
        kk[0] = fkey(v.x); kk[1] = fkey(v.y); kk[2] = fkey(v.z); kk[3] = fkey(v.w);
    }
    if (blockIdx.x == 0) {
        g_hist[tid] = 0u;
        if (tid == 0) { g_prefix = 0u; g_krem = K; if (ezero) *ezero = 0; }
    }
    gridbar(SCAN_NB);
    for (int pass = 0; pass < 4; pass++) {
        int shift = 24 - 8*pass;
        unsigned pfx = g_prefix;
        unsigned hm = pass ? (0xFFFFFFFFu << (shift+8)) : 0u;
        shist[tid] = 0u;
        __syncthreads();
        if (valid) {
            #pragma unroll
            for (int j = 0; j < 4; j++)
                if ((kk[j] & hm) == (pfx & hm))
                    atomicAdd(&shist[(kk[j] >> shift) & 0xFFu], 1u);
        }
        __syncthreads();
        unsigned c = shist[tid];
        if (c) atomicAdd((unsigned*)&g_hist[tid], c);
        gridbar(SCAN_NB);
        if (blockIdx.x == 0) {
            if (tid == 0) {
                unsigned k = (unsigned)g_krem, cum = 0; int b = 0;
                for (int i = 255; i >= 0; i--) {
                    unsigned h = g_hist[i];
                    if (cum + h >= k) { b = i; break; }
                    cum += h;
                }
                g_prefix = pfx | ((unsigned)b << shift);
                g_krem = (int)(k - cum);
            }
            __syncthreads();
            g_hist[tid] = 0u;
        }
        gridbar(SCAN_NB);
    }
    unsigned prefix = g_prefix; int krem = g_krem;
    int pk[4]; int s = 0;
    #pragma unroll
    for (int j = 0; j < 4; j++) {
        int g = 0, t = 0;
        if (valid) { g = (kk[j] > prefix) ? 1 : 0; t = (kk[j] == prefix) ? 1 : 0; }
        pk[j] = (g << 16) | t;
        s += pk[j];
    }
    int incl = blk_scan256(s, warpsum);
    if (tid == 255) d_partials[blockIdx.x] = incl;
    gridbar(SCAN_NB);
    if (blockIdx.x == 0 && tid < SCAN_NB) {
        int p = d_partials[tid];
        int t = p;
        #pragma unroll
        for (int o = 1; o < SCAN_NB; o <<= 1) {
            int q = __shfl_up_sync(0xFFFFFFFFu, t, o);
            if (tid >= o) t += q;
        }
        d_partials[tid] = t - p;
    }
    gridbar(SCAN_NB);
    int run = d_partials[blockIdx.x] + incl - s;
    if (valid) {
        #pragma unroll
        for (int j = 0; j < 4; j++) {
            int g_before = run >> 16, t_before = run & 0xFFFF;
            int g = pk[j] >> 16, t = pk[j] & 0xFFFF;
            int kp = g | (t && (t_before < krem));
            keep[i0+j] = kp;
            nid[i0+j]  = g_before + (t_before < krem ? t_before : krem);
            run += pk[j];
        }
    }
}

__global__ void k_pool_gather(const float* __restrict__ h, const float* __restrict__ score,
                              const int* __restrict__ keep, const int* __restrict__ nid,
                              float* __restrict__ out, int n, int F){
    int i = blockIdx.x*blockDim.x + threadIdx.x;
    if (i >= n*F) return;
    int node = i / F, c = i % F;
    if (keep[node]) out[(size_t)nid[node]*F + c] = h[i] * score[node];
}

__global__ void k_ecompact(const int* __restrict__ src, const int* __restrict__ dst,
                           const int* __restrict__ keep, const int* __restrict__ nid,
                           const int* pE, int Emax, int* __restrict__ ns,
                           int* __restrict__ nd, int* cntOut, int* deg){
    int e = blockIdx.x*blockDim.x + threadIdx.x;
    if (e >= Emax) return;
    int E = pE ? *pE : Emax;
    if (e >= E) return;
    int s = src[e], d = dst[e];
    if (keep[s] && keep[d]) {
        int j = atomicAdd(cntOut, 1);
        int nsd = nid[s], ndd = nid[d];
        ns[j] = nsd; nd[j] = ndd;
        atomicAdd(&deg[ndd], 1);
    }
}

// ---------------------------------------------------------------------------
// GAT
// ---------------------------------------------------------------------------
__device__ __forceinline__ float lrelu(float x){ return x > 0.f ? x : 0.2f*x; }

__global__ void k_gat_va(const float* __restrict__ gw, const float* __restrict__ as,
                         const float* __restrict__ ad, float* __restrict__ va){
    int t = blockIdx.x*blockDim.x + threadIdx.x;
    int w = t >> 5, lane = t & 31;
    if (w >= FIN*16) return;
    int k = w >> 4, col = w & 15;
    int h = col & 7;
    const float* avec = ((col < 8) ? as : ad) + h*H2c;
    const float* grow = gw + (size_t)k*(HEADSc*H2c) + h*H2c;
    float s = 0;
    for (int c = lane; c < H2c; c += 32) s += grow[c]*avec[c];
    #pragma unroll
    for (int o = 16; o; o >>= 1) s += __shfl_down_sync(0xFFFFFFFFu, s, o);
    if (!lane) va[k*16 + col] = s;
}

__global__ void k_gat_att(const int* __restrict__ rowptr, const int* __restrict__ csr,
                          const float* __restrict__ alad, float* __restrict__ att,
                          float* __restrict__ attself, int n){
    int t = blockIdx.x*blockDim.x + threadIdx.x;
    int node = t >> 3, h = t & 7;
    if (node >= n) return;
    int e0 = rowptr[node], e1 = rowptr[node+1];
    float add = alad[node*16 + 8 + h];
    float selfv = lrelu(alad[node*16 + h] + add);
    float m = selfv;
    for (int p = e0; p < e1; p++) {
        int s = csr[p];
        m = fmaxf(m, lrelu(alad[s*16 + h] + add));
    }
    float dn = expf(selfv - m);
    for (int p = e0; p < e1; p++) {
        int s = csr[p];
        float ex = expf(lrelu(alad[s*16 + h] + add) - m);
        att[p*8 + h] = ex;
        dn += ex;
    }
    float inv = 0.125f / dn;
    for (int p = e0; p < e1; p++) att[p*8 + h] *= inv;
    attself[node*8 + h] = expf(selfv - m) * inv;
}

__global__ void k_gat_gather(const int* __restrict__ rowptr, const int* __restrict__ csr,
                             const float* __restrict__ xh, const float* __restrict__ att,
                             const float* __restrict__ attself, const float* __restrict__ gb,
                             const float* __restrict__ hp2, float* __restrict__ gin, int n){
    int t = blockIdx.x*blockDim.x + threadIdx.x;
    int w = t >> 5, lane = t & 31;
    if (w >= n) return;
    int e0 = rowptr[w], e1 = rowptr[w+1];
    float acc0 = 0.f, acc1 = 0.f, acc2 = 0.f, acc3 = 0.f;
    {
        float av = (lane < 8) ? attself[w*8 + lane] : 0.f;
        const float* xr = xh + (size_t)w*(HEADSc*H2c);
        #pragma unroll
        for (int h = 0; h < HEADSc; h++) {
            float a = __shfl_sync(0xFFFFFFFFu, av, h);
            const float* r = xr + h*H2c;
            acc0 += a*r[lane]; acc1 += a*r[lane+32];
            acc2 += a*r[lane+64]; acc3 += a*r[lane+96];
        }
    }
    for (int p = e0; p < e1; p++) {
        float av = (lane < 8) ? att[p*8 + lane] : 0.f;
        int s = csr[p];
        const float* r = xh + (size_t)s*(HEADSc*H2c);
        #pragma unroll
        for (int h = 0; h < HEADSc; h++) {
            float a = __shfl_sync(0xFFFFFFFFu, av, h);
            const float* rh = r + h*H2c;
            acc0 += a*rh[lane]; acc1 += a*rh[lane+32];
            acc2 += a*rh[lane+64]; acc3 += a*rh[lane+96];
        }
    }
    const float* hr = hp2 + (size_t)w*H2c;
    float* gr = gin + (size_t)w*H2c;
    gr[lane]    = fmaxf(acc0 + gb[lane],    0.f) + hr[lane];
    gr[lane+32] = fmaxf(acc1 + gb[lane+32], 0.f) + hr[lane+32];
    gr[lane+64] = fmaxf(acc2 + gb[lane+64], 0.f) + hr[lane+64];
    gr[lane+96] = fmaxf(acc3 + gb[lane+96], 0.f) + hr[lane+96];
}

// ---------------------------------------------------------------------------
// GCN
// ---------------------------------------------------------------------------
__global__ void k_dinv(const int* __restrict__ deg, float* dinv, int n){
    int i = blockIdx.x*blockDim.x + threadIdx.x;
    if (i < n) dinv[i] = rsqrtf((float)(deg[i] + 1));
}

__global__ void k_gcn_gather(const int* __restrict__ rowptr, const int* __restrict__ csr,
                             const float* __restrict__ y, const float* __restrict__ dinv,
                             const float* __restrict__ b, float* __restrict__ o,
                             int n, int C, int relu){
    int t = blockIdx.x*blockDim.x + threadIdx.x;
    int w = t >> 5, lane = t & 31;
    if (w >= n) return;
    int e0 = rowptr[w], e1 = rowptr[w+1];
    float dd = dinv[w];
    float a0 = 0.f, a1 = 0.f;
    bool has2 = (lane + 32) < C;
    for (int p = e0; p < e1; p++) {
        int s = csr[p];
        float ds = dinv[s];
        a0 += ds * y[(size_t)s*C + lane];
        if (has2) a1 += ds * y[(size_t)s*C + lane + 32];
    }
    float v0 = dd*a0 + dd*dd*y[(size_t)w*C + lane] + b[lane];
    o[(size_t)w*C + lane] = relu ? fmaxf(v0, 0.f) : v0;
    if (has2) {
        float v1 = dd*a1 + dd*dd*y[(size_t)w*C + lane + 32] + b[lane+32];
        o[(size_t)w*C + lane + 32] = relu ? fmaxf(v1, 0.f) : v1;
    }
}

// ---------------------------------------------------------------------------
// Global mean pool + log_softmax (fused, persistent 40-block grid)
// ---------------------------------------------------------------------------
__global__ void k_colmean_lsm(const float* __restrict__ h, int rows, float* out){
    int c = blockIdx.x;
    float s = 0;
    for (int r = threadIdx.x; r < rows; r += 256) s += h[(size_t)r*NCc + c];
    __shared__ float sh[256];
    sh[threadIdx.x] = s; __syncthreads();
    for (int o = 128; o; o >>= 1) {
        if (threadIdx.x < o) sh[threadIdx.x] += sh[threadIdx.x + o];
        __syncthreads();
    }
    if (threadIdx.x == 0) g_gvec[c] = sh[0] / (float)rows;
    gridbar(CM_NB);
    if (blockIdx.x == 0 && threadIdx.x == 0) {
        float mxv = -1e30f;
        for (int i = 0; i < NCc; i++) mxv = fmaxf(mxv, g_gvec[i]);
        float ss = 0;
        for (int i = 0; i < NCc; i++) ss += expf(g_gvec[i] - mxv);
        float l = logf(ss);
        for (int i = 0; i < NCc; i++) out[i] = g_gvec[i] - mxv - l;
    }
}

// ---------------------------------------------------------------------------
// Host side
// ---------------------------------------------------------------------------
static void gemm_launch(const float* A, const float* B, const float* B2,
                        float* C, int M, int N, int K, int Nh){
    dim3 grid(CDIV(N, GBN), CDIV(M, GBM));
    k_gemm<<<grid, 256>>>(A, B, B2, C, M, N, K, Nh);
}

extern "C" void kernel_launch(void* const* d_in, const int* in_sizes, int n_in,
                              void* d_out, int out_size){
    const float* x    = (const float*)d_in[0];
    const int*   ei   = (const int*)  d_in[1];
    const float* s1wl = (const float*)d_in[3];
    const float* s1bl = (const float*)d_in[4];
    const float* s1wr = (const float*)d_in[5];
    const float* r1w  = (const float*)d_in[6];
    const float* r1b  = (const float*)d_in[7];
    const float* p1w  = (const float*)d_in[8];
    const float* s2wl = (const float*)d_in[9];
    const float* s2bl = (const float*)d_in[10];
    const float* s2wr = (const float*)d_in[11];
    const float* r2w  = (const float*)d_in[12];
    const float* r2b  = (const float*)d_in[13];
    const float* p2w  = (const float*)d_in[14];
    const float* gw   = (const float*)d_in[15];
    const float* gas  = (const float*)d_in[16];
    const float* gad  = (const float*)d_in[17];
    const float* gb   = (const float*)d_in[18];
    const float* g1w  = (const float*)d_in[19];
    const float* g1b  = (const float*)d_in[20];
    const float* g2w  = (const float*)d_in[21];
    const float* g2b  = (const float*)d_in[22];
    float* out = (float*)d_out;

    const int* src0 = ei;
    const int* dst0 = ei + Ee;

    float *aggr, *gP, *gQR, *h1, *hp1, *h2, *hp2, *xh, *va, *alad, *att, *attself;
    float *gin, *y1, *o1, *y2, *o2, *dinv, *score;
    int *cnt, *rowptr, *wp, *csr, *keep, *nid, *src1, *dst1, *src2, *dst2, *Ecnt;
    cudaGetSymbolAddress((void**)&aggr,    d_aggr);
    cudaGetSymbolAddress((void**)&cnt,     d_cnt);
    cudaGetSymbolAddress((void**)&rowptr,  d_rowptr);
    cudaGetSymbolAddress((void**)&wp,      d_wp);
    cudaGetSymbolAddress((void**)&csr,     d_csr);
    cudaGetSymbolAddress((void**)&gP,      d_gP);
    cudaGetSymbolAddress((void**)&gQR,     d_gQR);
    cudaGetSymbolAddress((void**)&h1,      d_h1);
    cudaGetSymbolAddress((void**)&hp1,     d_hp1);
    cudaGetSymbolAddress((void**)&h2,      d_h2);
    cudaGetSymbolAddress((void**)&hp2,     d_hp2);
    cudaGetSymbolAddress((void**)&xh,      d_xh);
    cudaGetSymbolAddress((void**)&va,      d_va);
    cudaGetSymbolAddress((void**)&alad,    d_alad);
    cudaGetSymbolAddress((void**)&att,     d_att);
    cudaGetSymbolAddress((void**)&attself, d_attself);
    cudaGetSymbolAddress((void**)&gin,     d_gin);
    cudaGetSymbolAddress((void**)&y1,      d_y1);
    cudaGetSymbolAddress((void**)&o1,      d_o1);
    cudaGetSymbolAddress((void**)&y2,      d_y2);
    cudaGetSymbolAddress((void**)&o2,      d_o2);
    cudaGetSymbolAddress((void**)&dinv,    d_dinv);
    cudaGetSymbolAddress((void**)&score,   d_score);
    cudaGetSymbolAddress((void**)&keep,    d_keep);
    cudaGetSymbolAddress((void**)&nid,     d_nid);
    cudaGetSymbolAddress((void**)&src1,    d_src1);
    cudaGetSymbolAddress((void**)&dst1,    d_dst1);
    cudaGetSymbolAddress((void**)&src2,    d_src2);
    cudaGetSymbolAddress((void**)&dst2,    d_dst2);
    cudaGetSymbolAddress((void**)&Ecnt,    d_Ecnt);

    const int ET_GRID = CDIV(Ee, 256);

    // ============ SAGE1 (128 -> 64): GEMM-first + CSR gather ============
    // cnt is zero here: static-init on first call, re-zeroed by exscans after.
    gemm_launch(x, s1wl, nullptr, gP, Nn, H1c, FIN, 0);
    k_count<<<ET_GRID, 256>>>(dst0, cnt, nullptr, Ee);
    k_exscan_p<<<SCAN_NB, 256>>>(cnt, rowptr, wp, Nn, Nn);
    k_fill<<<ET_GRID, 256>>>(src0, dst0, wp, csr, nullptr, Ee);
    gemm_launch(x, s1wr, r1w, gQR, Nn, 2*H1c, FIN, H1c);
    k_sage1_gather<<<CDIV(Nn*32, 256), 256>>>(rowptr, csr, gP, gQR, s1bl, r1b, h1, Nn);

    // ============ Pool 1 (N -> K1) ============
    k_score<<<CDIV(Nn, 8), 256>>>(h1, p1w, score, Nn, H1c);
    k_select_p<<<SCAN_NB, 256>>>(score, Nn, K1c, keep, nid, Ecnt);
    k_pool_gather<<<CDIV(Nn*H1c, 256), 256>>>(h1, score, keep, nid, hp1, Nn, H1c);
    k_ecompact<<<ET_GRID, 256>>>(src0, dst0, keep, nid, nullptr, Ee,
                                 src1, dst1, Ecnt, cnt);
    k_exscan_p<<<SCAN_NB, 256>>>(cnt, rowptr, wp, K1c, Nn);
    k_fill<<<ET_GRID, 256>>>(src1, dst1, wp, csr, Ecnt, Ee);

    // ============ SAGE2 (64 -> 128): gather-first ============
    k_mean_gather<<<CDIV(K1c*32, 256), 256>>>(rowptr, csr, hp1, aggr, K1c);
    gemm_launch(aggr, s2wl, nullptr, gP, K1c, H2c, H1c, 0);
    gemm_launch(hp1, s2wr, r2w, gQR, K1c, 2*H2c, H1c, H2c);
    k_sage_combine<<<CDIV(K1c*H2c, 256), 256>>>(gP, gQR, s2bl, r2b, h2, K1c, H2c);

    // ============ Pool 2 (K1 -> K2) + graph2 CSR ============
    k_score<<<CDIV(K1c, 8), 256>>>(h2, p2w, score, K1c, H2c);
    k_select_p<<<SCAN_NB, 256>>>(score, K1c, K2c, keep, nid, Ecnt + 1);
    k_pool_gather<<<CDIV(K1c*H2c, 256), 256>>>(h2, score, keep, nid, hp2, K1c, H2c);
    k_ecompact<<<ET_GRID, 256>>>(src1, dst1, keep, nid, Ecnt, Ee,
                                 src2, dst2, Ecnt + 1, cnt);
    k_dinv<<<CDIV(K2c, 256), 256>>>(cnt, dinv, K2c);
    k_exscan_p<<<SCAN_NB, 256>>>(cnt, rowptr, wp, K2c, Nn);
    k_fill<<<ET_GRID, 256>>>(src2, dst2, wp, csr, Ecnt + 1, Ee);

    // ============ GAT on K2 nodes ============
    k_gat_va<<<CDIV(FIN*16*32, 256), 256>>>(gw, gas, gad, va);
    gemm_launch(hp2, va, nullptr, alad, K2c, 16, H2c, 0);
    gemm_launch(hp2, gw, nullptr, xh, K2c, HEADSc*H2c, H2c, 0);
    k_gat_att<<<CDIV(K2c*8, 256), 256>>>(rowptr, csr, alad, att, attself, K2c);
    k_gat_gather<<<CDIV(K2c*32, 256), 256>>>(rowptr, csr, xh, att, attself, gb, hp2, gin, K2c);

    // ============ GCN1 (128 -> 64, relu) ============
    gemm_launch(gin, g1w, nullptr, y1, K2c, H1c, H2c, 0);
    k_gcn_gather<<<CDIV(K2c*32, 256), 256>>>(rowptr, csr, y1, dinv, g1b, o1, K2c, H1c, 1);

    // ============ GCN2 (64 -> 40) ============
    gemm_launch(o1, g2w, nullptr, y2, K2c, NCc, H1c, 0);
    k_gcn_gather<<<CDIV(K2c*32, 256), 256>>>(rowptr, csr, y2, dinv, g2b, o2, K2c, NCc, 0);

    // ============ Global mean pool + log_softmax (fused) ============
    k_colmean_lsm<<<CM_NB, 256>>>(o2, K2c, out);
}

// round 7
// speedup vs baseline: 1.2161x; 1.2161x over previous
#include <cuda_runtime.h>
#include <math.h>
#include <stdint.h>

#define Nn    20000
#define Ee    320000
#define FIN   128
#define H1c   64
#define H2c   128
#define HEADSc 8
#define NCc   40
#define K1c   16000
#define K2c   12800

#define CDIV(a,b) (((a)+(b)-1)/(b))

// ---------------------------------------------------------------------------
// Device scratch
// ---------------------------------------------------------------------------
__device__ float d_aggr[K1c*H1c];
__device__ int   d_cnt[Nn];
__device__ int   d_rowptr[Nn+1];
__device__ int   d_wp[Nn];
__device__ int   d_csr[Ee];
__device__ float d_gP[Nn*H2c];
__device__ float d_gQR[Nn*3*H1c > Nn*2*H2c ? Nn*3*H1c : Nn*2*H2c]; // SAGE1 Y[N,192] / SAGE2 QR[N,256]
__device__ float d_h1[Nn*H1c];
__device__ float d_hp1[K1c*H1c];
__device__ float d_h2[K1c*H2c];
__device__ float d_hp2[K2c*H2c];
__device__ float d_xh[K2c*HEADSc*H2c];     // 12800 x 1024
__device__ float d_va[FIN*16];
__device__ float d_alad[K2c*16];
__device__ float d_att[Ee*HEADSc];
__device__ float d_attself[K2c*HEADSc];
__device__ float d_gin[K2c*H2c];
__device__ float d_y1[K2c*H1c];
__device__ float d_o1[K2c*H1c];
__device__ float d_y2[K2c*NCc];
__device__ float d_o2[K2c*NCc];
__device__ float d_dinv[K2c];
__device__ float d_score[Nn];
__device__ int   d_keep[Nn];
__device__ int   d_nid[Nn];
__device__ int   d_src1[Ee], d_dst1[Ee], d_src2[Ee], d_dst2[Ee];
__device__ int   d_Ecnt[2];
__device__ float d_gvec[NCc];

// ---------------------------------------------------------------------------
// CSR build
// ---------------------------------------------------------------------------
__global__ void k_count(const int* __restrict__ dst, int* __restrict__ cnt,
                        const int* pE, int Emax){
    int e = blockIdx.x*blockDim.x + threadIdx.x;
    if (e >= Emax) return;
    int E = pE ? *pE : Emax;
    if (e < E) atomicAdd(&cnt[dst[e]], 1);
}

__device__ __forceinline__ int blk_scan_incl(int v, int tid, int* warpsum, int* total){
    __syncthreads();
    int lane = tid & 31, wid = tid >> 5;
    #pragma unroll
    for (int o = 1; o < 32; o <<= 1) {
        int t = __shfl_up_sync(0xFFFFFFFFu, v, o);
        if (lane >= o) v += t;
    }
    if (lane == 31) warpsum[wid] = v;
    __syncthreads();
    if (wid == 0) {
        int s = warpsum[lane];
        #pragma unroll
        for (int o = 1; o < 32; o <<= 1) {
            int t = __shfl_up_sync(0xFFFFFFFFu, s, o);
            if (lane >= o) s += t;
        }
        warpsum[lane] = s;
    }
    __syncthreads();
    *total = warpsum[31];
    return v + (wid ? warpsum[wid-1] : 0);
}

// single-block exclusive scan, 4 ints/thread/iter. Zeroes deg[0..nzero) after
// reading; optionally emits dinv[i] = rsqrt(deg[i]+1). n, nzero % 4 == 0.
__global__ void k_exscan(int* __restrict__ deg, int* __restrict__ rowptr,
                         int* __restrict__ wp, int n, int nzero,
                         float* __restrict__ dinvOut){
    __shared__ int warpsum[32];
    __shared__ int sh_run;
    int tid = threadIdx.x;                  // 1024 threads
    if (tid == 0) sh_run = 0;
    __syncthreads();
    int ntot = (n > nzero) ? n : nzero;
    for (int base = 0; base < ntot; base += 4096) {
        int i0 = base + tid*4;
        int4 v = make_int4(0,0,0,0);
        if (i0 < n) v = *reinterpret_cast<const int4*>(deg + i0);
        int s = v.x + v.y + v.z + v.w;
        int tot;
        int incl = blk_scan_incl(s, tid, warpsum, &tot);
        int run = sh_run + incl - s;
        if (i0 < n) {
            rowptr[i0]   = run; wp[i0]   = run; run += v.x;
            rowptr[i0+1] = run; wp[i0+1] = run; run += v.y;
            rowptr[i0+2] = run; wp[i0+2] = run; run += v.z;
            rowptr[i0+3] = run; wp[i0+3] = run;
            if (dinvOut) {
                dinvOut[i0]   = rsqrtf((float)(v.x + 1));
                dinvOut[i0+1] = rsqrtf((float)(v.y + 1));
                dinvOut[i0+2] = rsqrtf((float)(v.z + 1));
                dinvOut[i0+3] = rsqrtf((float)(v.w + 1));
            }
        }
        if (i0 < nzero) *reinterpret_cast<int4*>(deg + i0) = make_int4(0,0,0,0);
        __syncthreads();
        if (tid == 0) sh_run += tot;
        __syncthreads();
    }
    if (tid == 0) rowptr[n] = sh_run;
}

__global__ void k_fill(const int* __restrict__ src, const int* __restrict__ dst,
                       int* __restrict__ wp, int* __restrict__ csr,
                       const int* pE, int Emax){
    int e = blockIdx.x*blockDim.x + threadIdx.x;
    if (e >= Emax) return;
    int E = pE ? *pE : Emax;
    if (e >= E) return;
    int d = dst[e];
    int p = atomicAdd(&wp[d], 1);
    csr[p] = src[e];
}

// ---------------------------------------------------------------------------
// SAGE gathers
// ---------------------------------------------------------------------------
// SAGE1 fused on Y[N,192]: cols 0..63 = x@wl, 64..127 = x@wr, 128..191 = x@res
// h = relu(mean_nb(Y[:,0:64]) + Y[w,64:128] + bl) + Y[w,128:192] + rb
__global__ void k_sage1_gather(const int* __restrict__ rowptr, const int* __restrict__ csr,
                               const float* __restrict__ Y,
                               const float* __restrict__ bl, const float* __restrict__ rb,
                               float* __restrict__ h, int n){
    int t = blockIdx.x*blockDim.x + threadIdx.x;
    int w = t >> 5, lane = t & 31;
    if (w >= n) return;
    int e0 = rowptr[w], e1 = rowptr[w+1];
    float a0 = 0.f, a1 = 0.f;
    for (int p = e0; p < e1; p++) {
        const float* yr = Y + (size_t)csr[p]*192;
        a0 += yr[lane];
        a1 += yr[32 + lane];
    }
    float inv = 1.f / fmaxf((float)(e1 - e0), 1.f);
    a0 *= inv; a1 *= inv;
    const float* yw = Y + (size_t)w*192;
    h[w*H1c + lane]      = fmaxf(a0 + yw[64+lane] + bl[lane],    0.f) + yw[128+lane] + rb[lane];
    h[w*H1c + 32 + lane] = fmaxf(a1 + yw[96+lane] + bl[32+lane], 0.f) + yw[160+lane] + rb[32+lane];
}

__global__ void k_mean_gather(const int* __restrict__ rowptr, const int* __restrict__ csr,
                              const float* __restrict__ x, float* __restrict__ out, int n){
    int t = blockIdx.x*blockDim.x + threadIdx.x;
    int w = t >> 5, lane = t & 31;
    if (w >= n) return;
    int e0 = rowptr[w], e1 = rowptr[w+1];
    float a0 = 0.f, a1 = 0.f;
    for (int p = e0; p < e1; p++) {
        int s = csr[p];
        a0 += x[s*H1c + lane];
        a1 += x[s*H1c + 32 + lane];
    }
    float inv = 1.f / fmaxf((float)(e1 - e0), 1.f);
    out[w*H1c + lane]      = a0 * inv;
    out[w*H1c + 32 + lane] = a1 * inv;
}

__global__ void k_sage_combine(const float* __restrict__ P, const float* __restrict__ QR,
                               const float* __restrict__ bl, const float* __restrict__ rb,
                               float* __restrict__ h, int n, int C){
    int i = blockIdx.x*blockDim.x + threadIdx.x;
    if (i >= n*C) return;
    int node = i / C, c = i % C;
    const float* qr = QR + (size_t)node*2*C;
    float v = P[i] + qr[c] + bl[c];
    h[i] = fmaxf(v, 0.f) + qr[C + c] + rb[c];
}

// ---------------------------------------------------------------------------
// SGEMM: C = A@B, 128x128 tile, BK=16, double-buffered, 8x8/thread quadrants.
// Optional B2/B3 (multi-weight: each K x Nh; cols [0,Nh) from B, [Nh,2Nh) from
// B2, [2Nh,3Nh) from B3). K % 16 == 0.
// ---------------------------------------------------------------------------
#define GBM 128
#define GBN 128
#define GBK 16
__device__ __forceinline__ float bsel_load(const float* __restrict__ B,
                                           const float* __restrict__ B2,
                                           const float* __restrict__ B3,
                                           int gk, int gc, int N, int Nh){
    if (gc >= N) return 0.f;
    if (!B2) return B[(size_t)gk*N + gc];
    if (gc < Nh) return B[(size_t)gk*Nh + gc];
    if (!B3 || gc < 2*Nh) return B2[(size_t)gk*Nh + gc - Nh];
    return B3[(size_t)gk*Nh + gc - 2*Nh];
}

__global__ void __launch_bounds__(256)
k_gemm(const float* __restrict__ A, const float* __restrict__ B,
       const float* __restrict__ B2, const float* __restrict__ B3,
       float* __restrict__ C, int M, int N, int K, int Nh){
    __shared__ float As[2][GBK][GBM+4];
    __shared__ float Bs[2][GBK][GBN];
    int tid = threadIdx.x;                    // 256 threads
    int rowBase = blockIdx.y*GBM, colBase = blockIdx.x*GBN;
    int tr = tid >> 4, tc = tid & 15;
    int ar = tid >> 1, kseg = (tid & 1) * 8;
    int br = tid >> 4, bc0 = (tid & 15) * 8;
    float acc[8][8];
    #pragma unroll
    for (int i = 0; i < 8; i++)
        #pragma unroll
        for (int j = 0; j < 8; j++) acc[i][j] = 0.f;

    int nk = K / GBK;
    float4 pa0, pa1; float pb[8];
    {
        int gr = rowBase + ar;
        pa0 = make_float4(0.f,0.f,0.f,0.f); pa1 = pa0;
        if (gr < M) {
            pa0 = *reinterpret_cast<const float4*>(&A[(size_t)gr*K + kseg]);
            pa1 = *reinterpret_cast<const float4*>(&A[(size_t)gr*K + kseg + 4]);
        }
        #pragma unroll
        for (int j = 0; j < 8; j++)
            pb[j] = bsel_load(B, B2, B3, br, colBase + bc0 + j, N, Nh);
    }
    As[0][kseg+0][ar]=pa0.x; As[0][kseg+1][ar]=pa0.y; As[0][kseg+2][ar]=pa0.z; As[0][kseg+3][ar]=pa0.w;
    As[0][kseg+4][ar]=pa1.x; As[0][kseg+5][ar]=pa1.y; As[0][kseg+6][ar]=pa1.z; As[0][kseg+7][ar]=pa1.w;
    #pragma unroll
    for (int j = 0; j < 8; j++) Bs[0][br][bc0+j] = pb[j];
    __syncthreads();

    for (int kt = 0; kt < nk; kt++) {
        int cur = kt & 1;
        if (kt + 1 < nk) {
            int k0 = (kt+1)*GBK;
            int gr = rowBase + ar;
            pa0 = make_float4(0.f,0.f,0.f,0.f); pa1 = pa0;
            if (gr < M) {
                pa0 = *reinterpret_cast<const float4*>(&A[(size_t)gr*K + k0 + kseg]);
                pa1 = *reinterpret_cast<const float4*>(&A[(size_t)gr*K + k0 + kseg + 4]);
            }
            #pragma unroll
            for (int j = 0; j < 8; j++)
                pb[j] = bsel_load(B, B2, B3, k0 + br, colBase + bc0 + j, N, Nh);
        }
        #pragma unroll
        for (int kk = 0; kk < GBK; kk++) {
            float a[8], b[8];
            #pragma unroll
            for (int i = 0; i < 4; i++) { a[i] = As[cur][kk][tr*4+i]; a[4+i] = As[cur][kk][64+tr*4+i]; }
            #pragma unroll
            for (int j = 0; j < 4; j++) { b[j] = Bs[cur][kk][tc*4+j]; b[4+j] = Bs[cur][kk][64+tc*4+j]; }
            #pragma unroll
            for (int i = 0; i < 8; i++)
                #pragma unroll
                for (int j = 0; j < 8; j++) acc[i][j] += a[i]*b[j];
        }
        if (kt + 1 < nk) {
            int nb = 1 - cur;
            As[nb][kseg+0][ar]=pa0.x; As[nb][kseg+1][ar]=pa0.y; As[nb][kseg+2][ar]=pa0.z; As[nb][kseg+3][ar]=pa0.w;
            As[nb][kseg+4][ar]=pa1.x; As[nb][kseg+5][ar]=pa1.y; As[nb][kseg+6][ar]=pa1.z; As[nb][kseg+7][ar]=pa1.w;
            #pragma unroll
            for (int j = 0; j < 8; j++) Bs[nb][br][bc0+j] = pb[j];
        }
        __syncthreads();
    }
    #pragma unroll
    for (int i = 0; i < 8; i++) {
        int r = rowBase + ((i < 4) ? (tr*4 + i) : (64 + tr*4 + i - 4));
        if (r >= M) continue;
        #pragma unroll
        for (int j = 0; j < 8; j++) {
            int c = colBase + ((j < 4) ? (tc*4 + j) : (64 + tc*4 + j - 4));
            if (c < N) C[(size_t)r*N + c] = acc[i][j];
        }
    }
}

// ---------------------------------------------------------------------------
// TopK: score + single-block radix select (vectorized, packed single scan)
// ---------------------------------------------------------------------------
__global__ void k_score(const float* __restrict__ h, const float* __restrict__ w,
                        float* score, int n, int F){
    __shared__ float red[256];
    __shared__ float s_wni;
    float s = 0;
    for (int i = threadIdx.x; i < F; i += 256) { float v = w[i]; s += v*v; }
    red[threadIdx.x] = s; __syncthreads();
    for (int o = 128; o; o >>= 1) {
        if (threadIdx.x < o) red[threadIdx.x] += red[threadIdx.x+o];
        __syncthreads();
    }
    if (threadIdx.x == 0) s_wni = rsqrtf(red[0]);
    __syncthreads();
    int wrp = threadIdx.x >> 5, lane = threadIdx.x & 31;
    int node = blockIdx.x*8 + wrp;
    if (node >= n) return;
    const float* r = h + (size_t)node*F;
    float d = 0;
    for (int c = lane; c < F; c += 32) d += r[c]*w[c];
    #pragma unroll
    for (int o = 16; o; o >>= 1) d += __shfl_down_sync(0xFFFFFFFFu, d, o);
    if (!lane) score[node] = tanhf(d * s_wni);
}

__device__ __forceinline__ unsigned fkey(float f){
    unsigned u = __float_as_uint(f);
    return (u & 0x80000000u) ? ~u : (u | 0x80000000u);
}

// n must be a multiple of 4
__global__ void k_select(const float* __restrict__ score, int n, int K,
                         int* __restrict__ keep, int* __restrict__ nid, int* ezero){
    __shared__ unsigned hist[256];
    __shared__ int warpsum[32];
    __shared__ unsigned sh_prefix; __shared__ int sh_krem;
    __shared__ int sh_run;
    int tid = threadIdx.x;                     // 1024 threads
    if (tid == 0) { sh_prefix = 0u; sh_krem = K; if (ezero) *ezero = 0; }
    __syncthreads();
    for (int pass = 0; pass < 4; pass++) {
        if (tid < 256) hist[tid] = 0u;
        __syncthreads();
        int shift = 24 - 8*pass;
        unsigned pfx = sh_prefix;
        unsigned hm = (pass > 0) ? (0xFFFFFFFFu << (shift+8)) : 0u;
        for (int b = tid*4; b < n; b += 4096) {
            float4 v = *reinterpret_cast<const float4*>(score + b);
            unsigned k0 = fkey(v.x), k1 = fkey(v.y), k2 = fkey(v.z), k3 = fkey(v.w);
            if ((k0 & hm) == (pfx & hm)) atomicAdd(&hist[(k0 >> shift) & 0xFFu], 1u);
            if ((k1 & hm) == (pfx & hm)) atomicAdd(&hist[(k1 >> shift) & 0xFFu], 1u);
            if ((k2 & hm) == (pfx & hm)) atomicAdd(&hist[(k2 >> shift) & 0xFFu], 1u);
            if ((k3 & hm) == (pfx & hm)) atomicAdd(&hist[(k3 >> shift) & 0xFFu], 1u);
        }
        __syncthreads();
        if (tid == 0) {
            unsigned k = (unsigned)sh_krem, cum = 0; int b = 0;
            for (int i = 255; i >= 0; i--) {
                unsigned c = hist[i];
                if (cum + c >= k) { b = i; break; }
                cum += c;
            }
            sh_prefix = pfx | ((unsigned)b << shift);
            sh_krem = (int)(k - cum);
        }
        __syncthreads();
    }
    unsigned prefix = sh_prefix; int krem = sh_krem;
    if (tid == 0) sh_run = 0;
    __syncthreads();
    // single packed scan: p = (greater<<16) | tie
    for (int base = 0; base < n; base += 4096) {
        int i0 = base + tid*4;
        int pk[4]; int s = 0;
        unsigned kk[4];
        if (i0 < n) {
            float4 v = *reinterpret_cast<const float4*>(score + i0);
            kk[0] = fkey(v.x); kk[1] = fkey(v.y); kk[2] = fkey(v.z); kk[3] = fkey(v.w);
            #pragma unroll
            for (int j = 0; j < 4; j++) {
                int g = (kk[j] > prefix) ? 1 : 0;
                int t = (kk[j] == prefix) ? 1 : 0;
                pk[j] = (g << 16) | t;
                s += pk[j];
            }
        } else { pk[0]=pk[1]=pk[2]=pk[3]=0; }
        int tot;
        int incl = blk_scan_incl(s, tid, warpsum, &tot);
        int run = sh_run + incl - s;
        if (i0 < n) {
            #pragma unroll
            for (int j = 0; j < 4; j++) {
                int g_before = run >> 16, t_before = run & 0xFFFF;
                int g = pk[j] >> 16, t = pk[j] & 0xFFFF;
                int kp = g | (t && (t_before < krem));
                keep[i0+j] = kp;
                nid[i0+j]  = g_before + (t_before < krem ? t_before : krem);
                run += pk[j];
            }
        }
        __syncthreads();
        if (tid == 0) sh_run += tot;
        __syncthreads();
    }
}

__global__ void k_pool_gather(const float* __restrict__ h, const float* __restrict__ score,
                              const int* __restrict__ keep, const int* __restrict__ nid,
                              float* __restrict__ out, int n, int F){
    int i = blockIdx.x*blockDim.x + threadIdx.x;
    if (i >= n*F) return;
    int node = i / F, c = i % F;
    if (keep[node]) out[(size_t)nid[node]*F + c] = h[i] * score[node];
}

__global__ void k_ecompact(const int* __restrict__ src, const int* __restrict__ dst,
                           const int* __restrict__ keep, const int* __restrict__ nid,
                           const int* pE, int Emax, int* __restrict__ ns,
                           int* __restrict__ nd, int* cntOut, int* deg){
    int e = blockIdx.x*blockDim.x + threadIdx.x;
    if (e >= Emax) return;
    int E = pE ? *pE : Emax;
    if (e >= E) return;
    int s = src[e], d = dst[e];
    if (keep[s] && keep[d]) {
        int j = atomicAdd(cntOut, 1);
        int nsd = nid[s], ndd = nid[d];
        ns[j] = nsd; nd[j] = ndd;
        atomicAdd(&deg[ndd], 1);
    }
}

// ---------------------------------------------------------------------------
// GAT
// ---------------------------------------------------------------------------
__device__ __forceinline__ float lrelu(float x){ return x > 0.f ? x : 0.2f*x; }

__global__ void k_gat_va(const float* __restrict__ gw, const float* __restrict__ as,
                         const float* __restrict__ ad, float* __restrict__ va){
    int t = blockIdx.x*blockDim.x + threadIdx.x;
    int w = t >> 5, lane = t & 31;
    if (w >= FIN*16) return;
    int k = w >> 4, col = w & 15;
    int h = col & 7;
    const float* avec = ((col < 8) ? as : ad) + h*H2c;
    const float* grow = gw + (size_t)k*(HEADSc*H2c) + h*H2c;
    float s = 0;
    for (int c = lane; c < H2c; c += 32) s += grow[c]*avec[c];
    #pragma unroll
    for (int o = 16; o; o >>= 1) s += __shfl_down_sync(0xFFFFFFFFu, s, o);
    if (!lane) va[k*16 + col] = s;
}

__global__ void k_gat_att(const int* __restrict__ rowptr, const int* __restrict__ csr,
                          const float* __restrict__ alad, float* __restrict__ att,
                          float* __restrict__ attself, int n){
    int t = blockIdx.x*blockDim.x + threadIdx.x;
    int node = t >> 3, h = t & 7;
    if (node >= n) return;
    int e0 = rowptr[node], e1 = rowptr[node+1];
    float add = alad[node*16 + 8 + h];
    float selfv = lrelu(alad[node*16 + h] + add);
    float m = selfv;
    for (int p = e0; p < e1; p++) {
        int s = csr[p];
        m = fmaxf(m, lrelu(alad[s*16 + h] + add));
    }
    float dn = expf(selfv - m);
    for (int p = e0; p < e1; p++) {
        int s = csr[p];
        float ex = expf(lrelu(alad[s*16 + h] + add) - m);
        att[p*8 + h] = ex;
        dn += ex;
    }
    float inv = 0.125f / dn;
    for (int p = e0; p < e1; p++) att[p*8 + h] *= inv;
    attself[node*8 + h] = expf(selfv - m) * inv;
}

__global__ void k_gat_gather(const int* __restrict__ rowptr, const int* __restrict__ csr,
                             const float* __restrict__ xh, const float* __restrict__ att,
                             const float* __restrict__ attself, const float* __restrict__ gb,
                             const float* __restrict__ hp2, float* __restrict__ gin, int n){
    int t = blockIdx.x*blockDim.x + threadIdx.x;
    int w = t >> 5, lane = t & 31;
    if (w >= n) return;
    int e0 = rowptr[w], e1 = rowptr[w+1];
    float acc0 = 0.f, acc1 = 0.f, acc2 = 0.f, acc3 = 0.f;
    {
        float av = (lane < 8) ? attself[w*8 + lane] : 0.f;
        const float* xr = xh + (size_t)w*(HEADSc*H2c);
        #pragma unroll
        for (int h = 0; h < HEADSc; h++) {
            float a = __shfl_sync(0xFFFFFFFFu, av, h);
            const float* r = xr + h*H2c;
            acc0 += a*r[lane]; acc1 += a*r[lane+32];
            acc2 += a*r[lane+64]; acc3 += a*r[lane+96];
        }
    }
    for (int p = e0; p < e1; p++) {
        float av = (lane < 8) ? att[p*8 + lane] : 0.f;
        int s = csr[p];
        const float* r = xh + (size_t)s*(HEADSc*H2c);
        #pragma unroll
        for (int h = 0; h < HEADSc; h++) {
            float a = __shfl_sync(0xFFFFFFFFu, av, h);
            const float* rh = r + h*H2c;
            acc0 += a*rh[lane]; acc1 += a*rh[lane+32];
            acc2 += a*rh[lane+64]; acc3 += a*rh[lane+96];
        }
    }
    const float* hr = hp2 + (size_t)w*H2c;
    float* gr = gin + (size_t)w*H2c;
    gr[lane]    = fmaxf(acc0 + gb[lane],    0.f) + hr[lane];
    gr[lane+32] = fmaxf(acc1 + gb[lane+32], 0.f) + hr[lane+32];
    gr[lane+64] = fmaxf(acc2 + gb[lane+64], 0.f) + hr[lane+64];
    gr[lane+96] = fmaxf(acc3 + gb[lane+96], 0.f) + hr[lane+96];
}

// ---------------------------------------------------------------------------
// GCN
// ---------------------------------------------------------------------------
__global__ void k_gcn_gather(const int* __restrict__ rowptr, const int* __restrict__ csr,
                             const float* __restrict__ y, const float* __restrict__ dinv,
                             const float* __restrict__ b, float* __restrict__ o,
                             int n, int C, int relu){
    int t = blockIdx.x*blockDim.x + threadIdx.x;
    int w = t >> 5, lane = t & 31;
    if (w >= n) return;
    int e0 = rowptr[w], e1 = rowptr[w+1];
    float dd = dinv[w];
    float a0 = 0.f, a1 = 0.f;
    bool has2 = (lane + 32) < C;
    for (int p = e0; p < e1; p++) {
        int s = csr[p];
        float ds = dinv[s];
        a0 += ds * y[(size_t)s*C + lane];
        if (has2) a1 += ds * y[(size_t)s*C + lane + 32];
    }
    float v0 = dd*a0 + dd*dd*y[(size_t)w*C + lane] + b[lane];
    o[(size_t)w*C + lane] = relu ? fmaxf(v0, 0.f) : v0;
    if (has2) {
        float v1 = dd*a1 + dd*dd*y[(size_t)w*C + lane + 32] + b[lane+32];
        o[(size_t)w*C + lane + 32] = relu ? fmaxf(v1, 0.f) : v1;
    }
}

// ---------------------------------------------------------------------------
// Global mean pool + log_softmax
// ---------------------------------------------------------------------------
__global__ void k_colmean(const float* __restrict__ h, int rows, int C){
    int c = blockIdx.x;
    float s = 0;
    for (int r = threadIdx.x; r < rows; r += 256) s += h[(size_t)r*C + c];
    __shared__ float sh[256];
    sh[threadIdx.x] = s; __syncthreads();
    for (int o = 128; o; o >>= 1) {
        if (threadIdx.x < o) sh[threadIdx.x] += sh[threadIdx.x + o];
        __syncthreads();
    }
    if (threadIdx.x == 0) d_gvec[c] = sh[0] / (float)rows;
}
__global__ void k_lsm(float* out, int C){
    if (threadIdx.x == 0) {
        float mxv = -1e30f;
        for (int c = 0; c < C; c++) mxv = fmaxf(mxv, d_gvec[c]);
        float s = 0;
        for (int c = 0; c < C; c++) s += expf(d_gvec[c] - mxv);
        float l = logf(s);
        for (int c = 0; c < C; c++) out[c] = d_gvec[c] - mxv - l;
    }
}

// ---------------------------------------------------------------------------
// Host side
// ---------------------------------------------------------------------------
static void gemm_launch(const float* A, const float* B, const float* B2,
                        const float* B3, float* C, int M, int N, int K, int Nh){
    dim3 grid(CDIV(N, GBN), CDIV(M, GBM));
    k_gemm<<<grid, 256>>>(A, B, B2, B3, C, M, N, K, Nh);
}

extern "C" void kernel_launch(void* const* d_in, const int* in_sizes, int n_in,
                              void* d_out, int out_size){
    const float* x    = (const float*)d_in[0];
    const int*   ei   = (const int*)  d_in[1];
    const float* s1wl = (const float*)d_in[3];
    const float* s1bl = (const float*)d_in[4];
    const float* s1wr = (const float*)d_in[5];
    const float* r1w  = (const float*)d_in[6];
    const float* r1b  = (const float*)d_in[7];
    const float* p1w  = (const float*)d_in[8];
    const float* s2wl = (const float*)d_in[9];
    const float* s2bl = (const float*)d_in[10];
    const float* s2wr = (const float*)d_in[11];
    const float* r2w  = (const float*)d_in[12];
    const float* r2b  = (const float*)d_in[13];
    const float* p2w  = (const float*)d_in[14];
    const float* gw   = (const float*)d_in[15];
    const float* gas  = (const float*)d_in[16];
    const float* gad  = (const float*)d_in[17];
    const float* gb   = (const float*)d_in[18];
    const float* g1w  = (const float*)d_in[19];
    const float* g1b  = (const float*)d_in[20];
    const float* g2w  = (const float*)d_in[21];
    const float* g2b  = (const float*)d_in[22];
    float* out = (float*)d_out;

    const int* src0 = ei;
    const int* dst0 = ei + Ee;

    float *aggr, *gP, *gQR, *h1, *hp1, *h2, *hp2, *xh, *va, *alad, *att, *attself;
    float *gin, *y1, *o1, *y2, *o2, *dinv, *score;
    int *cnt, *rowptr, *wp, *csr, *keep, *nid, *src1, *dst1, *src2, *dst2, *Ecnt;
    cudaGetSymbolAddress((void**)&aggr,    d_aggr);
    cudaGetSymbolAddress((void**)&cnt,     d_cnt);
    cudaGetSymbolAddress((void**)&rowptr,  d_rowptr);
    cudaGetSymbolAddress((void**)&wp,      d_wp);
    cudaGetSymbolAddress((void**)&csr,     d_csr);
    cudaGetSymbolAddress((void**)&gP,      d_gP);
    cudaGetSymbolAddress((void**)&gQR,     d_gQR);
    cudaGetSymbolAddress((void**)&h1,      d_h1);
    cudaGetSymbolAddress((void**)&hp1,     d_hp1);
    cudaGetSymbolAddress((void**)&h2,      d_h2);
    cudaGetSymbolAddress((void**)&hp2,     d_hp2);
    cudaGetSymbolAddress((void**)&xh,      d_xh);
    cudaGetSymbolAddress((void**)&va,      d_va);
    cudaGetSymbolAddress((void**)&alad,    d_alad);
    cudaGetSymbolAddress((void**)&att,     d_att);
    cudaGetSymbolAddress((void**)&attself, d_attself);
    cudaGetSymbolAddress((void**)&gin,     d_gin);
    cudaGetSymbolAddress((void**)&y1,      d_y1);
    cudaGetSymbolAddress((void**)&o1,      d_o1);
    cudaGetSymbolAddress((void**)&y2,      d_y2);
    cudaGetSymbolAddress((void**)&o2,      d_o2);
    cudaGetSymbolAddress((void**)&dinv,    d_dinv);
    cudaGetSymbolAddress((void**)&score,   d_score);
    cudaGetSymbolAddress((void**)&keep,    d_keep);
    cudaGetSymbolAddress((void**)&nid,     d_nid);
    cudaGetSymbolAddress((void**)&src1,    d_src1);
    cudaGetSymbolAddress((void**)&dst1,    d_dst1);
    cudaGetSymbolAddress((void**)&src2,    d_src2);
    cudaGetSymbolAddress((void**)&dst2,    d_dst2);
    cudaGetSymbolAddress((void**)&Ecnt,    d_Ecnt);

    const int ET_GRID = CDIV(Ee, 256);

    // ============ SAGE1 (128 -> 64): one fused GEMM + CSR gather ============
    // cnt is zero here: static-init on first call, re-zeroed by exscans after.
    gemm_launch(x, s1wl, s1wr, r1w, gQR, Nn, 3*H1c, FIN, H1c);   // Y = x@[wl|wr|res]
    k_count<<<ET_GRID, 256>>>(dst0, cnt, nullptr, Ee);
    k_exscan<<<1, 1024>>>(cnt, rowptr, wp, Nn, Nn, nullptr);
    k_fill<<<ET_GRID, 256>>>(src0, dst0, wp, csr, nullptr, Ee);
    k_sage1_gather<<<CDIV(Nn*32, 256), 256>>>(rowptr, csr, gQR, s1bl, r1b, h1, Nn);

    // ============ Pool 1 (N -> K1) ============
    k_score<<<CDIV(Nn, 8), 256>>>(h1, p1w, score, Nn, H1c);
    k_select<<<1, 1024>>>(score, Nn, K1c, keep, nid, Ecnt);
    k_pool_gather<<<CDIV(Nn*H1c, 256), 256>>>(h1, score, keep, nid, hp1, Nn, H1c);
    k_ecompact<<<ET_GRID, 256>>>(src0, dst0, keep, nid, nullptr, Ee,
                                 src1, dst1, Ecnt, cnt);
    k_exscan<<<1, 1024>>>(cnt, rowptr, wp, K1c, Nn, nullptr);
    k_fill<<<ET_GRID, 256>>>(src1, dst1, wp, csr, Ecnt, Ee);

    // ============ SAGE2 (64 -> 128): gather-first ============
    k_mean_gather<<<CDIV(K1c*32, 256), 256>>>(rowptr, csr, hp1, aggr, K1c);
    gemm_launch(aggr, s2wl, nullptr, nullptr, gP, K1c, H2c, H1c, 0);
    gemm_launch(hp1, s2wr, r2w, nullptr, gQR, K1c, 2*H2c, H1c, H2c);
    k_sage_combine<<<CDIV(K1c*H2c, 256), 256>>>(gP, gQR, s2bl, r2b, h2, K1c, H2c);

    // ============ Pool 2 (K1 -> K2) + graph2 CSR + dinv ============
    k_score<<<CDIV(K1c, 8), 256>>>(h2, p2w, score, K1c, H2c);
    k_select<<<1, 1024>>>(score, K1c, K2c, keep, nid, Ecnt + 1);
    k_pool_gather<<<CDIV(K1c*H2c, 256), 256>>>(h2, score, keep, nid, hp2, K1c, H2c);
    k_ecompact<<<ET_GRID, 256>>>(src1, dst1, keep, nid, Ecnt, Ee,
                                 src2, dst2, Ecnt + 1, cnt);
    k_exscan<<<1, 1024>>>(cnt, rowptr, wp, K2c, Nn, dinv);
    k_fill<<<ET_GRID, 256>>>(src2, dst2, wp, csr, Ecnt + 1, Ee);

    // ============ GAT on K2 nodes ============
    k_gat_va<<<CDIV(FIN*16*32, 256), 256>>>(gw, gas, gad, va);
    gemm_launch(hp2, va, nullptr, nullptr, alad, K2c, 16, H2c, 0);
    gemm_launch(hp2, gw, nullptr, nullptr, xh, K2c, HEADSc*H2c, H2c, 0);
    k_gat_att<<<CDIV(K2c*8, 256), 256>>>(rowptr, csr, alad, att, attself, K2c);
    k_gat_gather<<<CDIV(K2c*32, 256), 256>>>(rowptr, csr, xh, att, attself, gb, hp2, gin, K2c);

    // ============ GCN1 (128 -> 64, relu) ============
    gemm_launch(gin, g1w, nullptr, nullptr, y1, K2c, H1c, H2c, 0);
    k_gcn_gather<<<CDIV(K2c*32, 256), 256>>>(rowptr, csr, y1, dinv, g1b, o1, K2c, H1c, 1);

    // ============ GCN2 (64 -> 40) ============
    gemm_launch(o1, g2w, nullptr, nullptr, y2, K2c, NCc, H1c, 0);
    k_gcn_gather<<<CDIV(K2c*32, 256), 256>>>(rowptr, csr, y2, dinv, g2b, o2, K2c, NCc, 0);

    // ============ Global mean pool + log_softmax ============
    k_colmean<<<NCc, 256>>>(o2, K2c, NCc);
    k_lsm<<<1, 32>>>(out, NCc);
}